// round 10
// baseline (speedup 1.0000x reference)
#include <cuda_runtime.h>
#include <cuda_bf16.h>
#include <cstdint>

// 3D Haar DWT, x: (B=2, C=32, D=64, H=128, W=128) fp32
// out: low (2,32,32,64,64) then highs (2,32,7,32,64,64), packed.
//
// FINAL champion (R2/R8 structure): direct per-thread float4 streaming with
// evict-first (.cs) hints both directions. Best measured across 9 structural
// variants: 74.7us kernel / 82.1us harness, DRAM 81.7% (6.48 TB/s).
// Traffic is minimal (512MB); ~81% DRAM utilization is the B300 controller
// ceiling for an interleaved 50/50 R/W stream mix — access-width, smem
// staging, persistence, and L1-policy variants all measured neutral or worse.

#define C_HAAR 0.35355339059327373f  // 1/(2*sqrt(2))

__global__ __launch_bounds__(256) void dwt3d_haar_kernel(
    const float* __restrict__ x, float* __restrict__ out)
{
    // total threads = 2,097,152 = 64(bc) * 32(d) * 64(h) * 16(wg)
    unsigned tid = blockIdx.x * 256u + threadIdx.x;
    unsigned wg = tid & 15u;          // w-group: 4 output w per group
    unsigned h  = (tid >> 4) & 63u;   // output h (0..63)
    unsigned d  = (tid >> 10) & 31u;  // output d (0..31)
    unsigned bc = tid >> 15;          // b*C + c (0..63)

    // input: ((bc)*64 + 2d+i)*16384 + (2h+j)*128 + 8*wg
    size_t in_base = ((size_t)bc << 20)
                   + ((size_t)d << 15)
                   + ((size_t)h << 8)
                   + (wg << 3);

    // Load 4 rows (i,j in {0,1}^2), 8 contiguous floats each (2x LDG.128),
    // streaming (evict-first) — no reuse anywhere.
    float4 r[4][2];
#pragma unroll
    for (int i = 0; i < 2; i++) {
#pragma unroll
        for (int j = 0; j < 2; j++) {
            const float4* p = reinterpret_cast<const float4*>(
                x + in_base + (size_t)i * 16384 + (size_t)j * 128);
            r[i * 2 + j][0] = __ldcs(p);
            r[i * 2 + j][1] = __ldcs(p + 1);
        }
    }

    // o[s][m]: subband s (i*4 + j*2 + k bits, 0=low-pass), output site m (0..3)
    float o[8][4];

#pragma unroll
    for (int m = 0; m < 4; m++) {
        float ka[2][2], kb[2][2];  // k-stage sum/diff
#pragma unroll
        for (int i = 0; i < 2; i++) {
#pragma unroll
            for (int j = 0; j < 2; j++) {
                float4 q = r[i * 2 + j][m >> 1];
                float v0 = (m & 1) ? q.z : q.x;
                float v1 = (m & 1) ? q.w : q.y;
                ka[i][j] = v0 + v1;
                kb[i][j] = v0 - v1;
            }
        }
        float t[2][2][2];  // t[x][y][i]: after j-stage
#pragma unroll
        for (int i = 0; i < 2; i++) {
            t[0][0][i] = ka[i][0] + ka[i][1];
            t[0][1][i] = ka[i][0] - ka[i][1];
            t[1][0][i] = kb[i][0] + kb[i][1];
            t[1][1][i] = kb[i][0] - kb[i][1];
        }
#pragma unroll
        for (int y = 0; y < 2; y++) {
#pragma unroll
            for (int xk = 0; xk < 2; xk++) {
                o[0 * 4 + y * 2 + xk][m] = C_HAAR * (t[xk][y][0] + t[xk][y][1]);
                o[1 * 4 + y * 2 + xk][m] = C_HAAR * (t[xk][y][0] - t[xk][y][1]);
            }
        }
    }

    // Output addresses: spatial = d*4096 + h*64 + 4*wg
    unsigned spatial = (d << 12) + (h << 6) + (wg << 2);

    // low: out[bc*131072 + spatial]
    {
        float4 v = make_float4(o[0][0], o[0][1], o[0][2], o[0][3]);
        __stcs(reinterpret_cast<float4*>(out + ((size_t)bc << 17) + spatial), v);
    }
    // highs: out[8388608 + (bc*7 + (s-1))*131072 + spatial]
#pragma unroll
    for (int s = 1; s < 8; s++) {
        float4 v = make_float4(o[s][0], o[s][1], o[s][2], o[s][3]);
        size_t off = 8388608u + ((size_t)(bc * 7u + (unsigned)(s - 1)) << 17) + spatial;
        __stcs(reinterpret_cast<float4*>(out + off), v);
    }
}

extern "C" void kernel_launch(void* const* d_in, const int* in_sizes, int n_in,
                              void* d_out, int out_size)
{
    const float* x = (const float*)d_in[0];
    float* out = (float*)d_out;
    dwt3d_haar_kernel<<<8192, 256>>>(x, out);
}

// round 11
// speedup vs baseline: 1.0207x; 1.0207x over previous
#include <cuda_runtime.h>
#include <cuda_bf16.h>
#include <cstdint>

// 3D Haar DWT, x: (B=2, C=32, D=64, H=128, W=128) fp32
// out: low (2,32,32,64,64) then highs (2,32,7,32,64,64), packed.
//
// R11 = champion (R2/R8) + store-order rotation by warp id: desynchronizes
// the 8 subband write streams across warps so all 8 output regions are
// written concurrently at every instant (instead of chip-wide lockstep
// phases), smoothing DRAM bank-group pressure.

#define C_HAAR 0.35355339059327373f  // 1/(2*sqrt(2))

__global__ __launch_bounds__(256) void dwt3d_haar_kernel(
    const float* __restrict__ x, float* __restrict__ out)
{
    // total threads = 2,097,152 = 64(bc) * 32(d) * 64(h) * 16(wg)
    unsigned tid = blockIdx.x * 256u + threadIdx.x;
    unsigned wg = tid & 15u;          // w-group: 4 output w per group
    unsigned h  = (tid >> 4) & 63u;   // output h (0..63)
    unsigned d  = (tid >> 10) & 31u;  // output d (0..31)
    unsigned bc = tid >> 15;          // b*C + c (0..63)

    // input: ((bc)*64 + 2d+i)*16384 + (2h+j)*128 + 8*wg
    size_t in_base = ((size_t)bc << 20)
                   + ((size_t)d << 15)
                   + ((size_t)h << 8)
                   + (wg << 3);

    // Load 4 rows (i,j in {0,1}^2), 8 contiguous floats each (2x LDG.128),
    // streaming (evict-first) — no reuse anywhere.
    float4 r[4][2];
#pragma unroll
    for (int i = 0; i < 2; i++) {
#pragma unroll
        for (int j = 0; j < 2; j++) {
            const float4* p = reinterpret_cast<const float4*>(
                x + in_base + (size_t)i * 16384 + (size_t)j * 128);
            r[i * 2 + j][0] = __ldcs(p);
            r[i * 2 + j][1] = __ldcs(p + 1);
        }
    }

    // o[s][m]: subband s (i*4 + j*2 + k bits, 0=low-pass), output site m (0..3)
    float o[8][4];

#pragma unroll
    for (int m = 0; m < 4; m++) {
        float ka[2][2], kb[2][2];  // k-stage sum/diff
#pragma unroll
        for (int i = 0; i < 2; i++) {
#pragma unroll
            for (int j = 0; j < 2; j++) {
                float4 q = r[i * 2 + j][m >> 1];
                float v0 = (m & 1) ? q.z : q.x;
                float v1 = (m & 1) ? q.w : q.y;
                ka[i][j] = v0 + v1;
                kb[i][j] = v0 - v1;
            }
        }
        float t[2][2][2];  // t[x][y][i]: after j-stage
#pragma unroll
        for (int i = 0; i < 2; i++) {
            t[0][0][i] = ka[i][0] + ka[i][1];
            t[0][1][i] = ka[i][0] - ka[i][1];
            t[1][0][i] = kb[i][0] + kb[i][1];
            t[1][1][i] = kb[i][0] - kb[i][1];
        }
#pragma unroll
        for (int y = 0; y < 2; y++) {
#pragma unroll
            for (int xk = 0; xk < 2; xk++) {
                o[0 * 4 + y * 2 + xk][m] = C_HAAR * (t[xk][y][0] + t[xk][y][1]);
                o[1 * 4 + y * 2 + xk][m] = C_HAAR * (t[xk][y][0] - t[xk][y][1]);
            }
        }
    }

    // Output addresses: spatial = d*4096 + h*64 + 4*wg
    unsigned spatial = (d << 12) + (h << 6) + (wg << 2);

    // Store all 8 subbands, starting at a warp-dependent rotation so the 8
    // write streams are concurrently active chip-wide.
    unsigned rot = (tid >> 5) & 7u;  // warp id mod 8
#pragma unroll
    for (int q = 0; q < 8; q++) {
        unsigned s = (q + rot) & 7u;
        float4 v = make_float4(o[s][0], o[s][1], o[s][2], o[s][3]);
        size_t off;
        if (s == 0) {
            off = ((size_t)bc << 17) + spatial;                              // low
        } else {
            off = 8388608u + ((size_t)(bc * 7u + (s - 1)) << 17) + spatial;  // highs
        }
        __stcs(reinterpret_cast<float4*>(out + off), v);
    }
}

extern "C" void kernel_launch(void* const* d_in, const int* in_sizes, int n_in,
                              void* d_out, int out_size)
{
    const float* x = (const float*)d_in[0];
    float* out = (float*)d_out;
    dwt3d_haar_kernel<<<8192, 256>>>(x, out);
}